// round 13
// baseline (speedup 1.0000x reference)
#include <cuda_runtime.h>
#include <cuda_bf16.h>

// N=256 rows, W=512 positions, 3 channels, K=64 buckets.
#define N_ROWS 256
#define WLEN   512
#define K      64
#define BT     96            // 3 warps; ONE WARP PER CHANNEL; 16 elements/lane
#define EPL    16

// One CTA per row; warp g owns channel g end-to-end — no intra-channel
// synchronization at all. Ballot histogram accumulates packed (pos|neg<<16)
// bucket counts directly in the owning lane's registers (lane L owns buckets
// {L, L+32}); two chained 5-step warp scans give exclusive prefixes; per-bucket
// float weights  wP=2PP+cP-p, wN=2PN+cN-q, wAll=2(PP+PN)+cP+cN-W  are kept in
// registers (packed 2x16-bit) and gathered per element via 3 variable-lane
// shuffles. Avg-rank identity:
//   S_pp=2Σ_pos h*wP, S_nn=2Σ_neg h*wN, S_all=2Σ h*wAll
//   loss_c = S_pp/(p²-p+1) + (1-(S_all-S_pp-S_nn)/(2pq+1)) + S_nn/(q²-q+1)
// One 3-warp __syncthreads, then tid0 writes out[n].
__global__ void __launch_bounds__(BT)
icl_kernel(const float* __restrict__ a_gt, const float* __restrict__ s_gt,
           const float* __restrict__ e_gt, const float* __restrict__ a_h,
           const float* __restrict__ s_h,  const float* __restrict__ e_h,
           float* __restrict__ out)
{
    __shared__ float lossCh[3];

    const int n    = blockIdx.x;
    const int g    = threadIdx.x >> 5;          // channel = warp id
    const int lane = threadIdx.x & 31;
    const int base = n * WLEN;

    const float* __restrict__ gt = (g == 0) ? a_gt : (g == 1) ? s_gt : e_gt;
    const float* __restrict__ ht = (g == 0) ? a_h  : (g == 1) ? s_h  : e_h;

    // ---- loads: 16 elements/lane as 4 coalesced float4 batches per array ----
    float    h[EPL];
    unsigned fmask = 0;                          // bit i = gt positive
    #pragma unroll
    for (int k = 0; k < 4; ++k) {
        const float4 hv = ((const float4*)(ht + base))[lane + 32 * k];
        const float4 gv = ((const float4*)(gt + base))[lane + 32 * k];
        h[4 * k + 0] = hv.x; h[4 * k + 1] = hv.y;
        h[4 * k + 2] = hv.z; h[4 * k + 3] = hv.w;
        fmask |= (gv.x > 0.5f ? 1u : 0u) << (4 * k + 0);
        fmask |= (gv.y > 0.5f ? 1u : 0u) << (4 * k + 1);
        fmask |= (gv.z > 0.5f ? 1u : 0u) << (4 * k + 2);
        fmask |= (gv.w > 0.5f ? 1u : 0u) << (4 * k + 3);
    }

    int b[EPL];
    #pragma unroll
    for (int i = 0; i < EPL; ++i) {
        int bi = (int)(h[i] * (float)K);
        b[i] = (bi > K - 1) ? (K - 1) : bi;
    }

    // ---- register ballot histogram: lane L owns buckets {L, L+32} ----
    int cl = 0, ch = 0;                          // packed pos | neg<<16
    #pragma unroll
    for (int i = 0; i < EPL; ++i) {
        const int bi = b[i];
        const unsigned r0 = __ballot_sync(0xFFFFFFFFu, bi & 1);
        const unsigned r1 = __ballot_sync(0xFFFFFFFFu, bi & 2);
        const unsigned r2 = __ballot_sync(0xFFFFFFFFu, bi & 4);
        const unsigned r3 = __ballot_sync(0xFFFFFFFFu, bi & 8);
        const unsigned r4 = __ballot_sync(0xFFFFFFFFu, bi & 16);
        const unsigned r5 = __ballot_sync(0xFFFFFFFFu, bi & 32);
        const unsigned rf = __ballot_sync(0xFFFFFFFFu, (fmask >> i) & 1u);

        unsigned m = (lane & 1  ? r0 : ~r0);
        m &=         (lane & 2  ? r1 : ~r1);
        m &=         (lane & 4  ? r2 : ~r2);
        m &=         (lane & 8  ? r3 : ~r3);
        m &=         (lane & 16 ? r4 : ~r4);
        const unsigned mLo = m & ~r5;
        const unsigned mHi = m &  r5;
        const int pL = __popc(mLo & rf);
        const int pH = __popc(mHi & rf);
        cl += pL + ((__popc(mLo) - pL) << 16);
        ch += pH + ((__popc(mHi) - pH) << 16);
    }

    // ---- two chained packed warp scans (buckets 0-31, then 32-63) ----
    int incL = cl, incH = ch;
    #pragma unroll
    for (int off = 1; off < 32; off <<= 1) {
        const int vL = __shfl_up_sync(0xFFFFFFFFu, incL, off);
        const int vH = __shfl_up_sync(0xFFFFFFFFu, incH, off);
        if (lane >= off) { incL += vL; incH += vH; }
    }
    const int totL  = __shfl_sync(0xFFFFFFFFu, incL, 31);
    const int totH  = __shfl_sync(0xFFFFFFFFu, incH, 31);
    const int total = totL + totH;               // packed p | q<<16 (no carry)
    const int p = total & 0xFFFF;
    const int q = total >> 16;

    const int prL = incL - cl;                   // packed exclusive prefixes
    const int prH = totL + incH - ch;

    // ---- per-bucket weights (2 buckets/lane), packed 2x16-bit ----
    int pkP, pkN, pkA;
    {
        const int cP0 = cl & 0xFFFF,  cN0 = cl >> 16;
        const int PP0 = prL & 0xFFFF, PN0 = prL >> 16;
        const int wP0 = 2 * PP0 + cP0 - p;
        const int wN0 = 2 * PN0 + cN0 - q;
        const int wA0 = 2 * (PP0 + PN0) + (cP0 + cN0) - WLEN;
        const int cP1 = ch & 0xFFFF,  cN1 = ch >> 16;
        const int PP1 = prH & 0xFFFF, PN1 = prH >> 16;
        const int wP1 = 2 * PP1 + cP1 - p;
        const int wN1 = 2 * PN1 + cN1 - q;
        const int wA1 = 2 * (PP1 + PN1) + (cP1 + cN1) - WLEN;
        pkP = (wP0 & 0xFFFF) | (wP1 << 16);      // |w| <= 1024: fits int16
        pkN = (wN0 & 0xFFFF) | (wN1 << 16);
        pkA = (wA0 & 0xFFFF) | (wA1 << 16);
    }

    // ---- gather weights via variable-lane shuffles; fp32 accumulate ----
    float app = 0.0f, ann = 0.0f, aall = 0.0f;
    #pragma unroll
    for (int i = 0; i < EPL; ++i) {
        const int owner = b[i] & 31;
        const int hi    = b[i] >> 5;
        const int aP = __shfl_sync(0xFFFFFFFFu, pkP, owner);
        const int aN = __shfl_sync(0xFFFFFFFFu, pkN, owner);
        const int aA = __shfl_sync(0xFFFFFFFFu, pkA, owner);
        const float wP = (float)(hi ? (aP >> 16) : (int)(short)(aP & 0xFFFF));
        const float wN = (float)(hi ? (aN >> 16) : (int)(short)(aN & 0xFFFF));
        const float wA = (float)(hi ? (aA >> 16) : (int)(short)(aA & 0xFFFF));
        if ((fmask >> i) & 1u) app += h[i] * wP;
        else                   ann += h[i] * wN;
        aall += h[i] * wA;
    }

    // ---- warp reduce (5 steps x 3) ----
    #pragma unroll
    for (int off = 16; off > 0; off >>= 1) {
        app  += __shfl_down_sync(0xFFFFFFFFu, app,  off);
        ann  += __shfl_down_sync(0xFFFFFFFFu, ann,  off);
        aall += __shfl_down_sync(0xFFFFFFFFu, aall, off);
    }

    if (lane == 0) {
        const float pf = (float)p, qf = (float)q;
        const float Apn = aall - app - ann;
        const float c1 = (2.0f * app) / (pf * (pf - 1.0f) + 1.0f);
        const float c2 = 1.0f - (2.0f * Apn) / (2.0f * pf * qf + 1.0f);
        const float c3 = (2.0f * ann) / (qf * (qf - 1.0f) + 1.0f);
        lossCh[g] = c1 + c2 + c3;
    }
    __syncthreads();                             // 3-warp barrier (cheap)

    if (threadIdx.x == 0)
        out[n] = lossCh[0] + lossCh[1] + lossCh[2];
}

extern "C" void kernel_launch(void* const* d_in, const int* in_sizes, int n_in,
                              void* d_out, int out_size)
{
    const float* a_gt = (const float*)d_in[0];
    const float* s_gt = (const float*)d_in[1];
    const float* e_gt = (const float*)d_in[2];
    const float* a_h  = (const float*)d_in[3];
    const float* s_h  = (const float*)d_in[4];
    const float* e_h  = (const float*)d_in[5];
    float* out = (float*)d_out;

    icl_kernel<<<N_ROWS, BT>>>(a_gt, s_gt, e_gt, a_h, s_h, e_h, out);
}